// round 1
// baseline (speedup 1.0000x reference)
#include <cuda_runtime.h>

// Time2Vec: out[b,l,d*64+e] = (e==0) ? x*W[d,0]+b[d,0] : sin(x*W[d,e]+b[d,e])
// x: (32,4096,8) fp32, W/b: (8,64) fp32, out: (32,4096,512) fp32.
// Streaming-store bound: ~256MB out + 4MB in -> ~33us HBM floor.

__global__ __launch_bounds__(256, 8)
void time2vec_kernel(const float* __restrict__ x,
                     const float* __restrict__ W,
                     const float* __restrict__ B,
                     float4* __restrict__ out,
                     int n_quads)
{
    __shared__ float sW[512];
    __shared__ float sB[512];
    for (int i = threadIdx.x; i < 512; i += blockDim.x) {
        sW[i] = W[i];
        sB[i] = B[i];
    }
    __syncthreads();

    int q = blockIdx.x * blockDim.x + threadIdx.x;
    if (q >= n_quads) return;

    int x_idx = q >> 4;          // 16 quads (64 floats) per x element
    int e     = (q & 15) << 2;   // starting e within [0,64)
    int d     = x_idx & 7;       // D = 8

    float xv = __ldg(&x[x_idx]); // broadcast within 16-thread group

    const float4 w4 = *reinterpret_cast<const float4*>(&sW[d * 64 + e]);
    const float4 b4 = *reinterpret_cast<const float4*>(&sB[d * 64 + e]);

    float4 r;
    float v0 = fmaf(xv, w4.x, b4.x);
    r.x = (e == 0) ? v0 : __sinf(v0);
    r.y = __sinf(fmaf(xv, w4.y, b4.y));
    r.z = __sinf(fmaf(xv, w4.z, b4.z));
    r.w = __sinf(fmaf(xv, w4.w, b4.w));

    out[q] = r;
}

extern "C" void kernel_launch(void* const* d_in, const int* in_sizes, int n_in,
                              void* d_out, int out_size)
{
    const float* x = (const float*)d_in[0];
    const float* W = (const float*)d_in[1];
    const float* B = (const float*)d_in[2];
    float4* out = (float4*)d_out;

    int n_quads = out_size / 4;  // 67,108,864 / 4 = 16,777,216
    int threads = 256;
    int blocks = (n_quads + threads - 1) / threads;
    time2vec_kernel<<<blocks, threads>>>(x, W, B, out, n_quads);
}

// round 2
// speedup vs baseline: 1.6412x; 1.6412x over previous
#include <cuda_runtime.h>

// Time2Vec: out[b,l,d*64+e] = (e==0) ? x*W[d,0]+b[d,0] : sin(x*W[d,e]+b[d,e])
// x: (32,4096,8) fp32, W/b: (8,64) fp32, out: (32,4096,512) fp32 = 16,777,216 quads.
//
// Structure: thread's quad index advances by STRIDE (multiple of 128 quads), so
// (d, e) are loop-invariant -> w4/b4 live in registers, zero shared traffic,
// inner loop = LDG.32 + 4 FFMA + 4 MUFU + STG.128.

constexpr int N_QUADS  = 1 << 24;       // 16,777,216
constexpr int THREADS  = 256;
constexpr int ITER     = 8;
constexpr int BLOCKS   = N_QUADS / (THREADS * ITER);   // 8192
constexpr int STRIDE   = BLOCKS * THREADS;             // 2,097,152 quads (mult of 128)
constexpr int XSTRIDE  = STRIDE >> 4;                  // 131,072 x-elements

__global__ __launch_bounds__(THREADS, 8)
void time2vec_kernel(const float* __restrict__ x,
                     const float* __restrict__ W,
                     const float* __restrict__ B,
                     float4* __restrict__ out)
{
    const int q0 = blockIdx.x * THREADS + threadIdx.x;

    // loop-invariant coordinates
    const int e = (q0 & 15) << 2;        // starting e within [0,64)
    const int d = (q0 >> 4) & 7;         // D = 8
    const bool first = (e == 0);         // this quad's .x is the passthrough lane

    const float4 w4 = __ldg((const float4*)(W + d * 64 + e));
    const float4 b4 = __ldg((const float4*)(B + d * 64 + e));

    const int x0 = q0 >> 4;

    #pragma unroll
    for (int i = 0; i < ITER; i++) {
        const float xv = __ldg(&x[x0 + i * XSTRIDE]);

        const float v0 = fmaf(xv, w4.x, b4.x);
        float4 r;
        r.x = first ? v0 : __sinf(v0);
        r.y = __sinf(fmaf(xv, w4.y, b4.y));
        r.z = __sinf(fmaf(xv, w4.z, b4.z));
        r.w = __sinf(fmaf(xv, w4.w, b4.w));

        out[q0 + i * STRIDE] = r;
    }
}

extern "C" void kernel_launch(void* const* d_in, const int* in_sizes, int n_in,
                              void* d_out, int out_size)
{
    const float* x = (const float*)d_in[0];
    const float* W = (const float*)d_in[1];
    const float* B = (const float*)d_in[2];
    time2vec_kernel<<<BLOCKS, THREADS>>>(x, W, B, (float4*)d_out);
}

// round 3
// speedup vs baseline: 1.6653x; 1.0147x over previous
#include <cuda_runtime.h>

// Time2Vec: out[b,l,d*64+e] = (e==0) ? x*W[d,0]+b[d,0] : sin(x*W[d,e]+b[d,e])
// x: (32,4096,8) fp32, W/b: (8,64) fp32, out: (32,4096,512) fp32 = 16,777,216 quads.
//
// Pure streaming kernel: 256MB write + 4MB read, zero L2 reuse value.
// -> evict-first cache hints on both streams (__ldcs / __stcs).
// Thread stride is a multiple of 128 quads, so (d,e) and w4/b4 are
// loop-invariant registers; inner body = LDG.32 + 4 FFMA + 4 MUFU + STG.128.

constexpr int N_QUADS  = 1 << 24;       // 16,777,216
constexpr int THREADS  = 256;
constexpr int ITER     = 8;
constexpr int BLOCKS   = N_QUADS / (THREADS * ITER);   // 8192
constexpr int STRIDE   = BLOCKS * THREADS;             // 2,097,152 quads (mult of 128)
constexpr int XSTRIDE  = STRIDE >> 4;                  // 131,072 x-elements

__global__ __launch_bounds__(THREADS, 8)
void time2vec_kernel(const float* __restrict__ x,
                     const float* __restrict__ W,
                     const float* __restrict__ B,
                     float4* __restrict__ out)
{
    const int q0 = blockIdx.x * THREADS + threadIdx.x;

    // loop-invariant coordinates
    const int e = (q0 & 15) << 2;        // starting e within [0,64)
    const int d = (q0 >> 4) & 7;         // D = 8
    const bool first = (e == 0);         // this quad's .x is the passthrough lane

    const float4 w4 = __ldg((const float4*)(W + d * 64 + e));
    const float4 b4 = __ldg((const float4*)(B + d * 64 + e));

    const int x0 = q0 >> 4;

    // front-batch the streaming x loads (evict-first: read exactly once)
    float xv[ITER];
    #pragma unroll
    for (int i = 0; i < ITER; i++)
        xv[i] = __ldcs(&x[x0 + i * XSTRIDE]);

    #pragma unroll
    for (int i = 0; i < ITER; i++) {
        const float v0 = fmaf(xv[i], w4.x, b4.x);
        float4 r;
        r.x = first ? v0 : __sinf(v0);
        r.y = __sinf(fmaf(xv[i], w4.y, b4.y));
        r.z = __sinf(fmaf(xv[i], w4.z, b4.z));
        r.w = __sinf(fmaf(xv[i], w4.w, b4.w));

        __stcs(&out[q0 + i * STRIDE], r);   // streaming store, evict-first
    }
}

extern "C" void kernel_launch(void* const* d_in, const int* in_sizes, int n_in,
                              void* d_out, int out_size)
{
    const float* x = (const float*)d_in[0];
    const float* W = (const float*)d_in[1];
    const float* B = (const float*)d_in[2];
    time2vec_kernel<<<BLOCKS, THREADS>>>(x, W, B, (float4*)d_out);
}

// round 4
// speedup vs baseline: 1.6889x; 1.0142x over previous
#include <cuda_runtime.h>

// Time2Vec: out[b,l,d*64+e] = (e==0) ? x*W[d,0]+b[d,0] : sin(x*W[d,e]+b[d,e])
// x: (32,4096,8) fp32, W/b: (8,64) fp32, out: (32,4096,512) fp32 = 16,777,216 quads.
//
// R3 lesson: giant per-thread strides (32MB) shredded DRAM row-buffer locality
// (9400 scattered write streams, DRAM=60% with idle cycles). Fix: each block
// owns ONE contiguous 32KB region; per-thread stride = THREADS = 256 quads,
// which is still a multiple of 128 -> (d,e) and w4/b4 remain loop-invariant.

constexpr int N_QUADS     = 1 << 24;                 // 16,777,216
constexpr int THREADS     = 256;
constexpr int ITER        = 8;
constexpr int BLOCK_QUADS = THREADS * ITER;          // 2048 quads = 32 KB contiguous
constexpr int BLOCKS      = N_QUADS / BLOCK_QUADS;   // 8192
constexpr int XITER       = THREADS / 16;            // 16 x-elements per iter step

__global__ __launch_bounds__(THREADS, 8)
void time2vec_kernel(const float* __restrict__ x,
                     const float* __restrict__ W,
                     const float* __restrict__ B,
                     float4* __restrict__ out)
{
    const int q0 = blockIdx.x * BLOCK_QUADS + threadIdx.x;

    // loop-invariant coordinates (block offset is a multiple of 2048,
    // per-iter stride 256 — both multiples of 128 quads)
    const int e = (q0 & 15) << 2;        // starting e within [0,64)
    const int d = (q0 >> 4) & 7;         // D = 8
    const bool first = (e == 0);         // this quad's .x is the passthrough lane

    const float4 w4 = __ldg((const float4*)(W + d * 64 + e));
    const float4 b4 = __ldg((const float4*)(B + d * 64 + e));

    const int x0 = q0 >> 4;

    // front-batch the streaming x loads (read exactly once)
    float xv[ITER];
    #pragma unroll
    for (int i = 0; i < ITER; i++)
        xv[i] = __ldcs(&x[x0 + i * XITER]);

    #pragma unroll
    for (int i = 0; i < ITER; i++) {
        const float v0 = fmaf(xv[i], w4.x, b4.x);
        float4 r;
        r.x = first ? v0 : __sinf(v0);
        r.y = __sinf(fmaf(xv[i], w4.y, b4.y));
        r.z = __sinf(fmaf(xv[i], w4.z, b4.z));
        r.w = __sinf(fmaf(xv[i], w4.w, b4.w));

        __stcs(&out[q0 + i * THREADS], r);   // dense 32KB per block
    }
}

extern "C" void kernel_launch(void* const* d_in, const int* in_sizes, int n_in,
                              void* d_out, int out_size)
{
    const float* x = (const float*)d_in[0];
    const float* W = (const float*)d_in[1];
    const float* B = (const float*)d_in[2];
    time2vec_kernel<<<BLOCKS, THREADS>>>(x, W, B, (float4*)d_out);
}